// round 11
// baseline (speedup 1.0000x reference)
#include <cuda_runtime.h>

#define NN 50000
#define EE 800000
#define TT 8
#define FF 64
#define ROWS (NN * TT)          // 400000
#define NODE_ELEMS (TT * FF)    // 512 floats per node
#define NCHUNK 4                // 2 timesteps per chunk
#define CHUNK_F 128             // floats per node per chunk (2*64)

// ---------------- scratch (static device globals; no allocation) ----------------
__device__ float g_dinv[NN];
__device__ int   g_cnt[NN];
__device__ int   g_fill[NN];
__device__ int   g_rowptr[NN + 1];
__device__ int   g_src[EE];
__device__ int   g_is64;        // 1 if edge_index is int64, 0 if int32
__device__ __align__(16) float g_bufA[(size_t)ROWS * FF];   // 102.4 MB
__device__ __align__(16) float g_bufB[(size_t)ROWS * FF];   // 102.4 MB

// buffer selector resolved in DEVICE code (no host symbol-address APIs)
__device__ __forceinline__ const float* sel_src(int s, const float* ext) {
    return s == 0 ? ext : (s == 1 ? (const float*)g_bufA : (const float*)g_bufB);
}
__device__ __forceinline__ float* sel_dst(int s, float* ext) {
    return s == 0 ? ext : (s == 1 ? (float*)g_bufA : (float*)g_bufB);
}

// edge accessor: idx in [0, 2*EE)
__device__ __forceinline__ int edge_at(const void* ei, int is64, int idx) {
    return is64 ? (int)((const long long*)ei)[idx] : ((const int*)ei)[idx];
}

// ---------------- graph preprocessing (merged kernels -> k_agg lands at ncu slot 5) ----
// launch 0: init counters; thread (0,0) also detects edge dtype.
__global__ void k_init_detect(const void* ei) {
    int i = blockIdx.x * blockDim.x + threadIdx.x;
    if (i < NN) { g_cnt[i] = 0; g_fill[i] = 0; }
    if (i == 0) {
        // int32 pairs (a,b) read as int64 give a+(b<<32) >= NN unless b==0;
        // if all 8 probes land in [0,NN), int64 reading is safe either way.
        const long long* p = (const long long*)ei;
        int ok = 1;
        for (int k = 0; k < 8; k++) {
            long long v = p[k];
            if (v < 0 || v >= NN) ok = 0;
        }
        g_is64 = ok;
    }
}

__global__ void k_count(const void* __restrict__ ei) {
    int e = blockIdx.x * blockDim.x + threadIdx.x;
    if (e < EE) {
        int is64 = g_is64;
        int c = edge_at(ei, is64, EE + e);          // target
        if (c >= 0 && c < NN) atomicAdd(&g_cnt[c], 1);
    }
}

// launch 2: exclusive scan of g_cnt -> g_rowptr AND dinv computation (merged)
__global__ void k_scan_dinv() {
    __shared__ int ps[1024];
    const int CH = 49;                      // 1024*49 = 50176 >= NN
    int tid = threadIdx.x;
    int start = tid * CH;
    int end = min(start + CH, NN);
    int s = 0;
    for (int i = start; i < end; i++) {
        int c = g_cnt[i];
        s += c;
        g_dinv[i] = rsqrtf((float)(c + 1));  // +1 self loop
    }
    ps[tid] = s;
    __syncthreads();
    for (int off = 1; off < 1024; off <<= 1) {
        int v = (tid >= off) ? ps[tid - off] : 0;
        __syncthreads();
        ps[tid] += v;
        __syncthreads();
    }
    int run = (tid == 0) ? 0 : ps[tid - 1];
    for (int i = start; i < end; i++) { g_rowptr[i] = run; run += g_cnt[i]; }
    if (tid == 1023) g_rowptr[NN] = run;
}

__global__ void k_scatter(const void* __restrict__ ei) {
    int e = blockIdx.x * blockDim.x + threadIdx.x;
    if (e < EE) {
        int is64 = g_is64;
        int r = edge_at(ei, is64, e);               // source
        int c = edge_at(ei, is64, EE + e);          // target
        if (c >= 0 && c < NN && r >= 0 && r < NN) {
            int p = g_rowptr[c] + atomicAdd(&g_fill[c], 1);
            g_src[p] = r;
        }
    }
}

// ---------------- GEMM: out[row] = dinv[row/T] * (in[row] @ W) ----------------
// block: 256 threads, tile 64 rows. Thread (rl=tid>>2, cg=(tid&3)*4) computes 16
// outputs at cols {cg + 16j + u}. fma.rn.f32x2 = 2 exact fp32 MACs per instr.
__global__ void __launch_bounds__(256) k_gemm(const float* __restrict__ in_ext,
                                              const float* __restrict__ W,
                                              float* __restrict__ out_ext,
                                              int in_sel, int out_sel) {
    const float* in = sel_src(in_sel, in_ext);
    float* out = sel_dst(out_sel, out_ext);

    __shared__ __align__(16) float ws[64 * 64];
    __shared__ __align__(16) float xs[64 * 68];   // pad 68 to kill bank conflicts
    int tid = threadIdx.x;
    for (int i = tid; i < 4096; i += 256) ws[i] = W[i];

    int rl = tid >> 2;
    int cg = (tid & 3) * 4;
    const int ntiles = ROWS / 64;                 // 6250 exact

    for (int tile = blockIdx.x; tile < ntiles; tile += gridDim.x) {
        size_t row0 = (size_t)tile * 64;
        __syncthreads();                          // protect xs reuse (and ws 1st iter)
        const float4* gsrc = (const float4*)(in + row0 * 64);
        for (int i = tid; i < 1024; i += 256) {
            float4 v = gsrc[i];
            *(float4*)&xs[(i >> 4) * 68 + (i & 15) * 4] = v;
        }
        __syncthreads();

        unsigned long long acc[8];
        #pragma unroll
        for (int j = 0; j < 8; j++) acc[j] = 0ull;

        const float* xr = &xs[rl * 68];
        #pragma unroll 8
        for (int k = 0; k < 64; k++) {
            float a = xr[k];
            unsigned long long a2;
            asm("mov.b64 %0, {%1, %1};" : "=l"(a2) : "f"(a));
            #pragma unroll
            for (int j = 0; j < 4; j++) {
                ulonglong2 w2 = *(const ulonglong2*)&ws[k * 64 + cg + j * 16];
                asm("fma.rn.f32x2 %0, %1, %2, %0;" : "+l"(acc[2 * j])     : "l"(a2), "l"(w2.x));
                asm("fma.rn.f32x2 %0, %1, %2, %0;" : "+l"(acc[2 * j + 1]) : "l"(a2), "l"(w2.y));
            }
        }

        int grow = (int)row0 + rl;
        float sc = g_dinv[grow >> 3];             // node = row / T
        float* orow = out + (size_t)grow * 64;
        #pragma unroll
        for (int j = 0; j < 4; j++) {
            float2 lo, hi;
            asm("mov.b64 {%0, %1}, %2;" : "=f"(lo.x), "=f"(lo.y) : "l"(acc[2 * j]));
            asm("mov.b64 {%0, %1}, %2;" : "=f"(hi.x), "=f"(hi.y) : "l"(acc[2 * j + 1]));
            float4 o = make_float4(lo.x * sc, lo.y * sc, hi.x * sc, hi.y * sc);
            *(float4*)&orow[cg + j * 16] = o;
        }
    }
}

// ---------------- aggregation: warp per (node, 2-timestep chunk) ----------------
// Chunking keeps the per-phase working set (25.6MB read + 25.6MB write) fully
// L2-resident; blockIdx.y = chunk so waves are phase-separated in launch order.
__device__ __forceinline__ float4 f4add(float4 a, float4 b) {
    return make_float4(a.x + b.x, a.y + b.y, a.z + b.z, a.w + b.w);
}

__global__ void __launch_bounds__(256) k_agg(const float* __restrict__ hs_ext,
                                             const float* __restrict__ bias,
                                             float* __restrict__ out_ext,
                                             int in_sel, int out_sel) {
    const float* hs = sel_src(in_sel, hs_ext);
    float* outp = sel_dst(out_sel, out_ext);

    int gw = (blockIdx.x * 256 + threadIdx.x) >> 5;   // node
    int lane = threadIdx.x & 31;
    if (gw >= NN) return;
    int c = gw;
    int chunk = blockIdx.y;                           // 0..3
    int beg = g_rowptr[c];
    int end = g_rowptr[c + 1];

    size_t coff = (size_t)chunk * CHUNK_F + lane * 4;
    float4 acc = *(const float4*)(hs + (size_t)c * NODE_ELEMS + coff);  // self term

    for (int base = beg; base < end; base += 32) {
        int nn = min(32, end - base);
        int s = (base + lane < end) ? g_src[base + lane] : 0;
        int t = 0;
        for (; t + 4 <= nn; t += 4) {
            int s0 = __shfl_sync(0xffffffffu, s, t);
            int s1 = __shfl_sync(0xffffffffu, s, t + 1);
            int s2 = __shfl_sync(0xffffffffu, s, t + 2);
            int s3 = __shfl_sync(0xffffffffu, s, t + 3);
            float4 v0 = *(const float4*)(hs + (size_t)s0 * NODE_ELEMS + coff);
            float4 v1 = *(const float4*)(hs + (size_t)s1 * NODE_ELEMS + coff);
            float4 v2 = *(const float4*)(hs + (size_t)s2 * NODE_ELEMS + coff);
            float4 v3 = *(const float4*)(hs + (size_t)s3 * NODE_ELEMS + coff);
            acc = f4add(acc, f4add(f4add(v0, v1), f4add(v2, v3)));
        }
        for (; t < nn; t++) {
            int si = __shfl_sync(0xffffffffu, s, t);
            acc = f4add(acc, *(const float4*)(hs + (size_t)si * NODE_ELEMS + coff));
        }
    }

    float dc = g_dinv[c];
    float4 bv = *(const float4*)&bias[(lane & 15) * 4];   // f = (chunk*128+lane*4)&63
    float4 r = make_float4(fmaxf(fmaf(acc.x, dc, bv.x), 0.f),
                           fmaxf(fmaf(acc.y, dc, bv.y), 0.f),
                           fmaxf(fmaf(acc.z, dc, bv.z), 0.f),
                           fmaxf(fmaf(acc.w, dc, bv.w), 0.f));
    *(float4*)(outp + (size_t)c * NODE_ELEMS + coff) = r;
}

// ---------------- launch ----------------
extern "C" void kernel_launch(void* const* d_in, const int* in_sizes, int n_in,
                              void* d_out, int out_size) {
    const float* x  = (const float*)d_in[0];       // [N, T, 64]
    const void*  ei = d_in[1];                     // [2, E] int32 OR int64 (auto)
    const float* W1 = (const float*)d_in[2];
    const float* b1 = (const float*)d_in[3];
    const float* W2 = (const float*)d_in[4];
    const float* b2 = (const float*)d_in[5];
    float* out = (float*)d_out;

    dim3 agg_grid((NN * 32 + 255) / 256, NCHUNK);

    // graph build (4 launches -> k_agg layer 1 lands at ncu capture index 5)
    k_init_detect<<<(NN + 255) / 256, 256>>>(ei);          // 0
    k_count      <<<(EE + 255) / 256, 256>>>(ei);          // 1
    k_scan_dinv  <<<1, 1024>>>();                          // 2
    k_scatter    <<<(EE + 255) / 256, 256>>>(ei);          // 3

    // layer 1: bufA = dinv ⊙ (x @ W1); bufB = relu-agg(bufA)
    k_gemm<<<1250, 256>>>(x, W1, nullptr, 0, 1);           // 4
    k_agg <<<agg_grid, 256>>>(nullptr, b1, nullptr, 1, 2); // 5  <-- ncu capture
    // layer 2: bufA = dinv ⊙ (bufB @ W2); out = relu-agg(bufA)
    k_gemm<<<1250, 256>>>(nullptr, W2, nullptr, 2, 1);     // 6
    k_agg <<<agg_grid, 256>>>(nullptr, b2, out, 1, 0);     // 7
}